// round 3
// baseline (speedup 1.0000x reference)
#include <cuda_runtime.h>
#include <cstdint>

// Problem constants (fixed by the reference)
#define SS 2048
#define DD 64
#define NBH 32          // B*H
#define QT 8            // queries per block
#define KC 64           // key chunk
#define NEGV (-1e9f)
#define SCL 0.125f      // 1/sqrt(64)

#define CTX_ELEMS (2LL*16*2048*64)      // 4,194,304
#define PROB_ELEMS (2LL*16*2048*2048)   // 134,217,728

// dynamic smem layout (floats):
//   q_s   [QT*DD]        = 512
//   sc    [QT*SS]        = 16384
//   stage [64*66]        = 4224   (K transposed chunk; reused flat for V chunk 64*64)
//   maskc [SS] bytes at the end
#define SM_QS    0
#define SM_SC    512
#define SM_STAGE (512 + QT*SS)
#define SM_FLOATS (512 + QT*SS + 64*66)
#define SMEM_BYTES (SM_FLOATS*4 + SS)

__global__ __launch_bounds__(256, 2)
void sdpa_fused_kernel(const float* __restrict__ Qg_,
                       const float* __restrict__ Kg_,
                       const float* __restrict__ Vg_,
                       const int*   __restrict__ Mg_,     // int32 bool mask (B, S)
                       float* __restrict__ ctx_out,
                       float* __restrict__ prob_out)
{
    extern __shared__ float smem[];
    float* q_s   = smem + SM_QS;
    float* sc    = smem + SM_SC;
    float* stage = smem + SM_STAGE;
    unsigned char* maskc = (unsigned char*)(smem + SM_FLOATS);

    const int bh = blockIdx.x >> 8;        // / (SS/QT) = /256
    const int qt = blockIdx.x & 255;
    const int q0 = qt * QT;
    const int b  = bh >> 4;
    const int tid = threadIdx.x;
    const int w = tid >> 5;                // warp id == local query
    const int l = tid & 31;                // lane

    const float* Qg = Qg_ + ((size_t)bh * SS + q0) * DD;
    const float* Kg = Kg_ + (size_t)bh * SS * DD;
    const float* Vg = Vg_ + (size_t)bh * SS * DD;
    const int*   mg = Mg_ + (size_t)b * SS;

    // ---- load Q tile (512 floats) + mask (2048 int32 -> bytes) ----
    {
        float2 v = ((const float2*)Qg)[tid];
        ((float2*)q_s)[tid] = v;
    }
    for (int i = tid; i < SS; i += 256) maskc[i] = (mg[i] != 0) ? 1 : 0;
    __syncthreads();

    // per-thread copy of this warp's query vector (registers)
    float qr[DD];
#pragma unroll
    for (int d = 0; d < DD; d++) qr[d] = q_s[w * DD + d];

    // ================= Phase 1: scores = (Q K^T)*scale, masked =================
    for (int c = 0; c < SS / KC; c++) {
        const int kb = c * KC;
        // stage K chunk transposed: stage[d*66 + k_local]
#pragma unroll
        for (int j = 0; j < 16; j++) {
            int e = j * 256 + tid;          // coalesced gmem (k-major rows of 64)
            int kk = e >> 6, d = e & 63;
            stage[d * 66 + kk] = Kg[(size_t)kb * DD + e];
        }
        __syncthreads();

        float acc0 = 0.f, acc1 = 0.f;       // keys 2l, 2l+1
#pragma unroll
        for (int d = 0; d < DD; d++) {
            float2 kv = *(const float2*)&stage[d * 66 + 2 * l];
            acc0 = fmaf(qr[d], kv.x, acc0);
            acc1 = fmaf(qr[d], kv.y, acc1);
        }
        int k0 = kb + 2 * l;
        float s0 = maskc[k0]     ? NEGV : acc0 * SCL;   // exact masked_fill semantics
        float s1 = maskc[k0 + 1] ? NEGV : acc1 * SCL;
        *(float2*)&sc[w * SS + k0] = make_float2(s0, s1);
        __syncthreads();
    }

    // ================= Phase 2: per-row softmax (warp w owns row w) ============
    float* row = sc + w * SS;
    float m = -3.0e38f;
    for (int j = l; j < SS; j += 32) m = fmaxf(m, row[j]);
#pragma unroll
    for (int o = 16; o; o >>= 1) m = fmaxf(m, __shfl_xor_sync(0xffffffffu, m, o));

    float sum = 0.f;
    for (int j = l; j < SS; j += 32) {
        float e = __expf(row[j] - m);
        row[j] = e;                         // keep UNNORMALIZED in smem
        sum += e;
    }
#pragma unroll
    for (int o = 16; o; o >>= 1) sum += __shfl_xor_sync(0xffffffffu, sum, o);
    float inv = 1.0f / sum;

    if (prob_out) {
        float* pg = prob_out + ((size_t)bh * SS + (q0 + w)) * SS;
        for (int j = l; j < SS; j += 32) pg[j] = row[j] * inv;
    }

    // ================= Phase 3: context = P V (unnormalized, scale at end) =====
    float a0 = 0.f, a1 = 0.f;               // dims 2l, 2l+1
    for (int c = 0; c < SS / KC; c++) {
        const int kb = c * KC;
        __syncthreads();                    // prior chunk consumed / softmax done
#pragma unroll
        for (int j = 0; j < 16; j++) {
            int e = j * 256 + tid;          // vs[k][d] flat, coalesced both sides
            stage[e] = Vg[(size_t)kb * DD + e];
        }
        __syncthreads();
#pragma unroll 8
        for (int kk = 0; kk < KC; kk++) {
            float p = row[kb + kk];         // broadcast
            float2 vv = *(const float2*)&stage[kk * DD + 2 * l];
            a0 = fmaf(p, vv.x, a0);
            a1 = fmaf(p, vv.y, a1);
        }
    }
    if (ctx_out) {
        float2 o = make_float2(a0 * inv, a1 * inv);
        ((float2*)(ctx_out + ((size_t)bh * SS + q0 + w) * DD))[l] = o;
    }
}

extern "C" void kernel_launch(void* const* d_in, const int* in_sizes, int n_in,
                              void* d_out, int out_size)
{
    const float* Q = (const float*)d_in[0];
    const float* K = (const float*)d_in[1];
    const float* V = (const float*)d_in[2];
    const int*   M = (const int*)d_in[3];   // bool mask materialized as int32

    float* ctx = nullptr;
    float* prob = nullptr;
    long long os = out_size;
    if (os >= (long long)(CTX_ELEMS + PROB_ELEMS)) {        // (context, attn_prob) tuple
        ctx  = (float*)d_out;
        prob = (float*)d_out + CTX_ELEMS;
    } else if (os == (long long)PROB_ELEMS) {               // prob only (defensive)
        prob = (float*)d_out;
    } else {                                                // context only (defensive)
        ctx  = (float*)d_out;
    }

    static bool attr_set = false;
    if (!attr_set) {
        cudaFuncSetAttribute(sdpa_fused_kernel,
                             cudaFuncAttributeMaxDynamicSharedMemorySize, SMEM_BYTES);
        attr_set = true;
    }

    dim3 grid(NBH * (SS / QT));   // 8192 blocks
    sdpa_fused_kernel<<<grid, 256, SMEM_BYTES>>>(Q, K, V, M, ctx, prob);
}

// round 4
// speedup vs baseline: 2.3061x; 2.3061x over previous
#include <cuda_runtime.h>
#include <cuda_bf16.h>
#include <cstdint>

#define SS 2048
#define DD 64
#define NBH 32
#define QT 16           // queries per block
#define KCH 128         // key chunk
#define NEGV (-1e9f)
#define SCL 0.125f

#define CTX_ELEMS (2LL*16*2048*64)
#define PROB_ELEMS (2LL*16*2048*2048)

// ---------------- bf16 split scratch for K and V (device globals: allowed) ----
__device__ __nv_bfloat16 g_khi[NBH*SS*DD];
__device__ __nv_bfloat16 g_klo[NBH*SS*DD];
__device__ __nv_bfloat16 g_vhi[NBH*SS*DD];
__device__ __nv_bfloat16 g_vlo[NBH*SS*DD];

__global__ void prep_split_kernel(const float* __restrict__ K,
                                  const float* __restrict__ V)
{
    int i = blockIdx.x * 256 + threadIdx.x;   // grid covers NBH*SS*DD exactly
    float k = K[i];
    __nv_bfloat16 kh = __float2bfloat16(k);
    g_khi[i] = kh;
    g_klo[i] = __float2bfloat16(k - __bfloat162float(kh));
    float v = V[i];
    __nv_bfloat16 vh = __float2bfloat16(v);
    g_vhi[i] = vh;
    g_vlo[i] = __float2bfloat16(v - __bfloat162float(vh));
}

// ---------------- smem layout (bytes) ----------------------------------------
// sc    float[16][2052]          131328
// qhi   bf16 [16][72]              2304
// qlo   bf16 [16][72]              2304
// kvhi  bf16 [128][72]            18432   (K chunk in phase1, V chunk in phase3)
// kvlo  bf16 [128][72]            18432
// phi   bf16 [16][136]             4352
// plo   bf16 [16][136]             4352
// mask  uchar[2048]                2048
// rinv  float[16]                    64
#define OFF_SC    0
#define OFF_QHI   131328
#define OFF_QLO   (OFF_QHI + 2304)
#define OFF_KVHI  (OFF_QLO + 2304)
#define OFF_KVLO  (OFF_KVHI + 18432)
#define OFF_PHI   (OFF_KVLO + 18432)
#define OFF_PLO   (OFF_PHI + 4352)
#define OFF_MASK  (OFF_PLO + 4352)
#define OFF_RINV  (OFF_MASK + 2048)
#define SMEM_BYTES (OFF_RINV + 64)

__device__ __forceinline__ uint32_t sptr(const void* p) {
    return (uint32_t)__cvta_generic_to_shared(p);
}
__device__ __forceinline__ void ldmA(uint32_t* a, uint32_t addr) {
    asm volatile("ldmatrix.sync.aligned.m8n8.x4.shared.b16 {%0,%1,%2,%3}, [%4];"
                 : "=r"(a[0]), "=r"(a[1]), "=r"(a[2]), "=r"(a[3]) : "r"(addr));
}
__device__ __forceinline__ void ldmB(uint32_t* b, uint32_t addr) {
    asm volatile("ldmatrix.sync.aligned.m8n8.x2.shared.b16 {%0,%1}, [%2];"
                 : "=r"(b[0]), "=r"(b[1]) : "r"(addr));
}
__device__ __forceinline__ void ldmBT(uint32_t* b, uint32_t addr) {
    asm volatile("ldmatrix.sync.aligned.m8n8.x2.trans.shared.b16 {%0,%1}, [%2];"
                 : "=r"(b[0]), "=r"(b[1]) : "r"(addr));
}
__device__ __forceinline__ void mma16816(float* c, const uint32_t* a, const uint32_t* b) {
    asm volatile("mma.sync.aligned.m16n8k16.row.col.f32.bf16.bf16.f32 "
                 "{%0,%1,%2,%3}, {%4,%5,%6,%7}, {%8,%9}, {%0,%1,%2,%3};"
                 : "+f"(c[0]), "+f"(c[1]), "+f"(c[2]), "+f"(c[3])
                 : "r"(a[0]), "r"(a[1]), "r"(a[2]), "r"(a[3]), "r"(b[0]), "r"(b[1]));
}

__global__ __launch_bounds__(256, 1)
void sdpa_mma_kernel(const float* __restrict__ Qg_,
                     const int*   __restrict__ Mg_,
                     float* __restrict__ ctx_out,
                     float* __restrict__ prob_out)
{
    extern __shared__ char smem[];
    float*          sc    = (float*)(smem + OFF_SC);
    __nv_bfloat16*  qhi_s = (__nv_bfloat16*)(smem + OFF_QHI);
    __nv_bfloat16*  qlo_s = (__nv_bfloat16*)(smem + OFF_QLO);
    __nv_bfloat16*  kvhi  = (__nv_bfloat16*)(smem + OFF_KVHI);
    __nv_bfloat16*  kvlo  = (__nv_bfloat16*)(smem + OFF_KVLO);
    __nv_bfloat16*  phi_s = (__nv_bfloat16*)(smem + OFF_PHI);
    __nv_bfloat16*  plo_s = (__nv_bfloat16*)(smem + OFF_PLO);
    unsigned char*  maskc = (unsigned char*)(smem + OFF_MASK);
    float*          rinv  = (float*)(smem + OFF_RINV);

    const int tid = threadIdx.x;
    const int w   = tid >> 5;
    const int l   = tid & 31;
    const int bh  = blockIdx.x >> 7;     // / 128 q-tiles
    const int qt  = blockIdx.x & 127;
    const int q0  = qt * QT;
    const int b   = bh >> 4;

    const float* Qg = Qg_ + ((size_t)bh * SS + q0) * DD;
    const int*   mg = Mg_ + (size_t)b * SS;

    // ---- Q tile load + split; mask load ----
    for (int i = tid; i < QT * DD; i += 256) {
        int r = i >> 6, d = i & 63;
        float x = Qg[i];
        __nv_bfloat16 h = __float2bfloat16(x);
        qhi_s[r * 72 + d] = h;
        qlo_s[r * 72 + d] = __float2bfloat16(x - __bfloat162float(h));
    }
    for (int i = tid; i < SS; i += 256) maskc[i] = (mg[i] != 0) ? 1 : 0;

    // ldmatrix base addresses (per-lane)
    const uint32_t qA_hi = sptr(qhi_s) + (l & 15) * 144 + (l >> 4) * 16;
    const uint32_t qA_lo = sptr(qlo_s) + (l & 15) * 144 + (l >> 4) * 16;
    const uint32_t kB_off = (l & 7) * 144 + ((l >> 3) & 1) * 16;
    const uint32_t pA_hi = sptr(phi_s) + (l & 15) * 272 + (l >> 4) * 16;
    const uint32_t pA_lo = sptr(plo_s) + (l & 15) * 272 + (l >> 4) * 16;
    const uint32_t vB_hi = sptr(kvhi) + (l & 15) * 144 + w * 16;
    const uint32_t vB_lo = sptr(kvlo) + (l & 15) * 144 + w * 16;

    // ================= Phase 1: scores via MMA ==============================
    for (int ch = 0; ch < SS / KCH; ch++) {
        const int kb = ch * KCH;
        __syncthreads();
        {
            const uint4* srh = (const uint4*)(g_khi + ((size_t)bh * SS + kb) * DD);
            const uint4* srl = (const uint4*)(g_klo + ((size_t)bh * SS + kb) * DD);
#pragma unroll
            for (int i = tid; i < KCH * DD / 8; i += 256) {   // 1024 uint4
                int key = i >> 3, seg = i & 7;
                *(uint4*)(kvhi + key * 72 + seg * 8) = srh[i];
                *(uint4*)(kvlo + key * 72 + seg * 8) = srl[i];
            }
        }
        __syncthreads();

        float accM[2][4] = {}, accL[2][4] = {};
        uint32_t ah[4], al[4], bh2[2], bl2[2];
#pragma unroll
        for (int kt = 0; kt < 4; kt++) {
            ldmA(ah, qA_hi + kt * 32);
            ldmA(al, qA_lo + kt * 32);
#pragma unroll
            for (int t = 0; t < 2; t++) {
                uint32_t n0e = (16 * w + 8 * t) * 144;
                ldmB(bh2, sptr(kvhi) + n0e + kB_off + kt * 32);
                ldmB(bl2, sptr(kvlo) + n0e + kB_off + kt * 32);
                mma16816(accM[t], ah, bh2);
                mma16816(accL[t], ah, bl2);
                mma16816(accL[t], al, bh2);
            }
        }
        // epilogue: scale + mask -> sc
        int r = l >> 2;
#pragma unroll
        for (int t = 0; t < 2; t++) {
            int cb = kb + 16 * w + 8 * t + (l & 3) * 2;
            float o0 = accM[t][0] + accL[t][0];
            float o1 = accM[t][1] + accL[t][1];
            float o2 = accM[t][2] + accL[t][2];
            float o3 = accM[t][3] + accL[t][3];
            bool m0 = maskc[cb], m1 = maskc[cb + 1];
            *(float2*)(sc + r * 2052 + cb) =
                make_float2(m0 ? NEGV : o0 * SCL, m1 ? NEGV : o1 * SCL);
            *(float2*)(sc + (r + 8) * 2052 + cb) =
                make_float2(m0 ? NEGV : o2 * SCL, m1 ? NEGV : o3 * SCL);
        }
    }
    __syncthreads();

    // ================= Phase 2: softmax (warp w -> rows 2w, 2w+1) ===========
#pragma unroll
    for (int rr = 0; rr < 2; rr++) {
        int r = 2 * w + rr;
        float* row = sc + r * 2052;
        float m = -3.0e38f;
        for (int j = 4 * l; j < SS; j += 128) {
            float4 v = *(float4*)(row + j);
            m = fmaxf(m, fmaxf(fmaxf(v.x, v.y), fmaxf(v.z, v.w)));
        }
#pragma unroll
        for (int o = 16; o; o >>= 1) m = fmaxf(m, __shfl_xor_sync(0xffffffffu, m, o));
        float s = 0.f;
        for (int j = 4 * l; j < SS; j += 128) {
            float4 v = *(float4*)(row + j);
            v.x = __expf(v.x - m); v.y = __expf(v.y - m);
            v.z = __expf(v.z - m); v.w = __expf(v.w - m);
            s += (v.x + v.y) + (v.z + v.w);
            *(float4*)(row + j) = v;            // keep UNNORMALIZED
        }
#pragma unroll
        for (int o = 16; o; o >>= 1) s += __shfl_xor_sync(0xffffffffu, s, o);
        float inv = 1.0f / s;
        if (l == 0) rinv[r] = inv;
        if (prob_out) {
            float* pg = prob_out + ((size_t)bh * SS + q0 + r) * SS;
            for (int j = 4 * l; j < SS; j += 128) {
                float4 v = *(float4*)(row + j);
                v.x *= inv; v.y *= inv; v.z *= inv; v.w *= inv;
                *(float4*)(pg + j) = v;
            }
        }
    }

    // ================= Phase 3: context = P V via MMA =======================
    float ovM[4] = {}, ovL[4] = {};
    for (int ch = 0; ch < SS / KCH; ch++) {
        const int kb = ch * KCH;
        __syncthreads();
        {
            const uint4* srh = (const uint4*)(g_vhi + ((size_t)bh * SS + kb) * DD);
            const uint4* srl = (const uint4*)(g_vlo + ((size_t)bh * SS + kb) * DD);
#pragma unroll
            for (int i = tid; i < KCH * DD / 8; i += 256) {
                int key = i >> 3, seg = i & 7;
                *(uint4*)(kvhi + key * 72 + seg * 8) = srh[i];
                *(uint4*)(kvlo + key * 72 + seg * 8) = srl[i];
            }
        }
        // convert P chunk to bf16 hi/lo
        for (int i = tid; i < QT * KCH; i += 256) {
            int r = i >> 7, c = i & 127;
            float p = sc[r * 2052 + kb + c];
            __nv_bfloat16 h = __float2bfloat16(p);
            phi_s[r * 136 + c] = h;
            plo_s[r * 136 + c] = __float2bfloat16(p - __bfloat162float(h));
        }
        __syncthreads();

        uint32_t ah[4], al[4], bh2[2], bl2[2];
#pragma unroll
        for (int kt = 0; kt < 8; kt++) {
            ldmA(ah, pA_hi + kt * 32);
            ldmA(al, pA_lo + kt * 32);
            ldmBT(bh2, vB_hi + kt * 2304);      // 16 keys * 144B
            ldmBT(bl2, vB_lo + kt * 2304);
            mma16816(ovM, ah, bh2);
            mma16816(ovL, ah, bl2);
            mma16816(ovL, al, bh2);
        }
    }

    if (ctx_out) {
        int r = l >> 2;
        int cb = 8 * w + (l & 3) * 2;
        float i0 = rinv[r], i1 = rinv[r + 8];
        *(float2*)(ctx_out + ((size_t)bh * SS + q0 + r) * DD + cb) =
            make_float2((ovM[0] + ovL[0]) * i0, (ovM[1] + ovL[1]) * i0);
        *(float2*)(ctx_out + ((size_t)bh * SS + q0 + r + 8) * DD + cb) =
            make_float2((ovM[2] + ovL[2]) * i1, (ovM[3] + ovL[3]) * i1);
    }
}

extern "C" void kernel_launch(void* const* d_in, const int* in_sizes, int n_in,
                              void* d_out, int out_size)
{
    const float* Q = (const float*)d_in[0];
    const float* K = (const float*)d_in[1];
    const float* V = (const float*)d_in[2];
    const int*   M = (const int*)d_in[3];

    float* ctx = nullptr;
    float* prob = nullptr;
    long long os = out_size;
    if (os >= (long long)(CTX_ELEMS + PROB_ELEMS)) {
        ctx  = (float*)d_out;
        prob = (float*)d_out + CTX_ELEMS;
    } else if (os == (long long)PROB_ELEMS) {
        prob = (float*)d_out;
    } else {
        ctx  = (float*)d_out;
    }

    static bool attr_set = false;
    if (!attr_set) {
        cudaFuncSetAttribute(sdpa_mma_kernel,
                             cudaFuncAttributeMaxDynamicSharedMemorySize, SMEM_BYTES);
        attr_set = true;
    }

    prep_split_kernel<<<(NBH * SS * DD) / 256, 256>>>(K, V);
    sdpa_mma_kernel<<<NBH * (SS / QT), 256, SMEM_BYTES>>>(Q, M, ctx, prob);
}

// round 5
// speedup vs baseline: 4.1053x; 1.7802x over previous
#include <cuda_runtime.h>
#include <cuda_bf16.h>
#include <cstdint>

#define SS 2048
#define DD 64
#define NBH 32
#define QT 32           // queries per block
#define KCH 64          // key chunk
#define SCL 0.125f

#define CTX_ELEMS (2LL*16*2048*64)
#define PROB_ELEMS (2LL*16*2048*2048)

// ---------------- device-global scratch (allowed) -----------------------------
__device__ __nv_bfloat16 g_khi[NBH*SS*DD];
__device__ __nv_bfloat16 g_klo[NBH*SS*DD];
__device__ __nv_bfloat16 g_vhi[NBH*SS*DD];
__device__ __nv_bfloat16 g_vlo[NBH*SS*DD];
__device__ float g_inv[NBH*SS];

__global__ void prep_split_kernel(const float* __restrict__ K,
                                  const float* __restrict__ V)
{
    int i = blockIdx.x * 256 + threadIdx.x;
    float k = K[i];
    __nv_bfloat16 kh = __float2bfloat16(k);
    g_khi[i] = kh;
    g_klo[i] = __float2bfloat16(k - __bfloat162float(kh));
    float v = V[i];
    __nv_bfloat16 vh = __float2bfloat16(v);
    g_vhi[i] = vh;
    g_vlo[i] = __float2bfloat16(v - __bfloat162float(vh));
}

// ---------------- smem layout (bytes), rows padded to 72 bf16 (144B) ---------
#define OFF_QHI  0                    // 32*72*2 = 4608
#define OFF_QLO  4608
#define OFF_KHI  9216                 // 64*72*2 = 9216
#define OFF_KLO  18432
#define OFF_VHI  27648
#define OFF_VLO  36864
#define OFF_PHI  46080                // 32*72*2 = 4608
#define OFF_PLO  50688
#define OFF_MASK 55296                // 2048
#define OFF_RSUM 57344                // 32*4
#define SMEM_BYTES (57344 + 128)

__device__ __forceinline__ uint32_t sptr(const void* p) {
    return (uint32_t)__cvta_generic_to_shared(p);
}
__device__ __forceinline__ void ldmA(uint32_t* a, uint32_t addr) {
    asm volatile("ldmatrix.sync.aligned.m8n8.x4.shared.b16 {%0,%1,%2,%3}, [%4];"
                 : "=r"(a[0]), "=r"(a[1]), "=r"(a[2]), "=r"(a[3]) : "r"(addr));
}
__device__ __forceinline__ void ldmB(uint32_t* b, uint32_t addr) {
    asm volatile("ldmatrix.sync.aligned.m8n8.x2.shared.b16 {%0,%1}, [%2];"
                 : "=r"(b[0]), "=r"(b[1]) : "r"(addr));
}
__device__ __forceinline__ void ldmBT(uint32_t* b, uint32_t addr) {
    asm volatile("ldmatrix.sync.aligned.m8n8.x2.trans.shared.b16 {%0,%1}, [%2];"
                 : "=r"(b[0]), "=r"(b[1]) : "r"(addr));
}
__device__ __forceinline__ void mma16816(float* c, const uint32_t* a, const uint32_t* b) {
    asm volatile("mma.sync.aligned.m16n8k16.row.col.f32.bf16.bf16.f32 "
                 "{%0,%1,%2,%3}, {%4,%5,%6,%7}, {%8,%9}, {%0,%1,%2,%3};"
                 : "+f"(c[0]), "+f"(c[1]), "+f"(c[2]), "+f"(c[3])
                 : "r"(a[0]), "r"(a[1]), "r"(a[2]), "r"(a[3]), "r"(b[0]), "r"(b[1]));
}

__global__ __launch_bounds__(256, 3)
void sdpa_stream_kernel(const float* __restrict__ Qg_,
                        const int*   __restrict__ Mg_,
                        float* __restrict__ ctx_out,
                        float* __restrict__ prob_out)
{
    extern __shared__ char smem[];
    __nv_bfloat16* qhi_s = (__nv_bfloat16*)(smem + OFF_QHI);
    __nv_bfloat16* qlo_s = (__nv_bfloat16*)(smem + OFF_QLO);
    __nv_bfloat16* khi_s = (__nv_bfloat16*)(smem + OFF_KHI);
    __nv_bfloat16* klo_s = (__nv_bfloat16*)(smem + OFF_KLO);
    __nv_bfloat16* vhi_s = (__nv_bfloat16*)(smem + OFF_VHI);
    __nv_bfloat16* vlo_s = (__nv_bfloat16*)(smem + OFF_VLO);
    __nv_bfloat16* phi_s = (__nv_bfloat16*)(smem + OFF_PHI);
    __nv_bfloat16* plo_s = (__nv_bfloat16*)(smem + OFF_PLO);
    unsigned char* maskc = (unsigned char*)(smem + OFF_MASK);
    float*         rsum_s = (float*)(smem + OFF_RSUM);

    const int tid = threadIdx.x;
    const int w = tid >> 5, l = tid & 31;
    const int bh = blockIdx.x >> 6;
    const int qt = blockIdx.x & 63;
    const int q0 = qt * QT;
    const int b = bh >> 4;
    const int mh = w & 1;        // m-half (rows 16*mh..)
    const int ns = w >> 1;       // 16-col slice

    const float* Qg = Qg_ + ((size_t)bh * SS + q0) * DD;
    const int*   mg = Mg_ + (size_t)b * SS;

    // ---- load Q (split bf16) + mask; zero rowsums ----
    for (int i = tid; i < QT * DD; i += 256) {
        int r = i >> 6, d = i & 63;
        float x = Qg[i];
        __nv_bfloat16 h = __float2bfloat16(x);
        qhi_s[r * 72 + d] = h;
        qlo_s[r * 72 + d] = __float2bfloat16(x - __bfloat162float(h));
    }
    for (int i = tid; i < SS; i += 256) maskc[i] = (mg[i] != 0) ? 1 : 0;
    if (tid < QT) rsum_s[tid] = 0.f;

    // per-lane fragment addresses
    const uint32_t qA_hi = sptr(qhi_s) + (16 * mh + (l & 15)) * 144 + (l >> 4) * 16;
    const uint32_t qA_lo = sptr(qlo_s) + (16 * mh + (l & 15)) * 144 + (l >> 4) * 16;
    const uint32_t pA_hi = sptr(phi_s) + (16 * mh + (l & 15)) * 144 + (l >> 4) * 16;
    const uint32_t pA_lo = sptr(plo_s) + (16 * mh + (l & 15)) * 144 + (l >> 4) * 16;
    const uint32_t kOff  = (l & 7) * 144 + ((l >> 3) & 1) * 16;
    const uint32_t vOff  = (l & 15) * 144;
    const int r0 = 16 * mh + (l >> 2);

    float pvM[2][4] = {}, pvL[2][4] = {};
    float rs0 = 0.f, rs1 = 0.f;

    for (int ch = 0; ch < SS / KCH; ch++) {
        const int kb = ch * KCH;
        __syncthreads();   // prior chunk's MMAs done with K/V/P smem
        {
            const uint4* kh = (const uint4*)(g_khi + ((size_t)bh * SS + kb) * DD);
            const uint4* kl = (const uint4*)(g_klo + ((size_t)bh * SS + kb) * DD);
            const uint4* vh = (const uint4*)(g_vhi + ((size_t)bh * SS + kb) * DD);
            const uint4* vl = (const uint4*)(g_vlo + ((size_t)bh * SS + kb) * DD);
#pragma unroll
            for (int i = tid; i < KCH * DD / 8; i += 256) {   // 512 uint4 per array
                int key = i >> 3, sg = i & 7;
                int dst = key * 72 + sg * 8;
                *(uint4*)(khi_s + dst) = kh[i];
                *(uint4*)(klo_s + dst) = kl[i];
                *(uint4*)(vhi_s + dst) = vh[i];
                *(uint4*)(vlo_s + dst) = vl[i];
            }
        }
        __syncthreads();

        // ---- QK^T: warp computes rows 16mh..+15, cols 16ns..+15 (2 n8 tiles)
        float accM[2][4] = {}, accL[2][4] = {};
        uint32_t ah[4], al[4], bhf[2], blf[2];
#pragma unroll
        for (int kt = 0; kt < 4; kt++) {
            ldmA(ah, qA_hi + kt * 32);
            ldmA(al, qA_lo + kt * 32);
#pragma unroll
            for (int t = 0; t < 2; t++) {
                uint32_t nb = (16 * ns + 8 * t) * 144 + kOff + kt * 32;
                ldmB(bhf, sptr(khi_s) + nb);
                ldmB(blf, sptr(klo_s) + nb);
                mma16816(accM[t], ah, bhf);
                mma16816(accL[t], ah, blf);
                mma16816(accL[t], al, bhf);
            }
        }

        // ---- epilogue: scale, mask, exp (no max needed), prob out, P->smem
#pragma unroll
        for (int t = 0; t < 2; t++) {
            int cl = 16 * ns + 8 * t + (l & 3) * 2;
            int cg = kb + cl;
            bool m0 = maskc[cg], m1 = maskc[cg + 1];
            float p0 = m0 ? 0.f : __expf((accM[t][0] + accL[t][0]) * SCL);
            float p1 = m1 ? 0.f : __expf((accM[t][1] + accL[t][1]) * SCL);
            float p2 = m0 ? 0.f : __expf((accM[t][2] + accL[t][2]) * SCL);
            float p3 = m1 ? 0.f : __expf((accM[t][3] + accL[t][3]) * SCL);
            rs0 += p0 + p1;
            rs1 += p2 + p3;
            if (prob_out) {
                *(float2*)(prob_out + ((size_t)bh * SS + q0 + r0) * SS + cg) =
                    make_float2(p0, p1);
                *(float2*)(prob_out + ((size_t)bh * SS + q0 + r0 + 8) * SS + cg) =
                    make_float2(p2, p3);
            }
            __nv_bfloat16 h0 = __float2bfloat16(p0), h1 = __float2bfloat16(p1);
            __nv_bfloat16 h2 = __float2bfloat16(p2), h3 = __float2bfloat16(p3);
            *(__nv_bfloat162*)(phi_s + r0 * 72 + cl) =
                __nv_bfloat162(h0, h1);
            *(__nv_bfloat162*)(plo_s + r0 * 72 + cl) =
                __nv_bfloat162(__float2bfloat16(p0 - __bfloat162float(h0)),
                               __float2bfloat16(p1 - __bfloat162float(h1)));
            *(__nv_bfloat162*)(phi_s + (r0 + 8) * 72 + cl) =
                __nv_bfloat162(h2, h3);
            *(__nv_bfloat162*)(plo_s + (r0 + 8) * 72 + cl) =
                __nv_bfloat162(__float2bfloat16(p2 - __bfloat162float(h2)),
                               __float2bfloat16(p3 - __bfloat162float(h3)));
        }
        __syncthreads();   // P ready

        // ---- PV: warp computes rows 16mh..+15, dims 16ns..+15 (2 n8 tiles)
#pragma unroll
        for (int kt = 0; kt < 4; kt++) {
            ldmA(ah, pA_hi + kt * 32);
            ldmA(al, pA_lo + kt * 32);
#pragma unroll
            for (int t = 0; t < 2; t++) {
                uint32_t vb = kt * 2304 + vOff + (2 * ns + t) * 16;
                ldmBT(bhf, sptr(vhi_s) + vb);
                ldmBT(blf, sptr(vlo_s) + vb);
                mma16816(pvM[t], ah, bhf);
                mma16816(pvL[t], ah, blf);
                mma16816(pvL[t], al, bhf);
            }
        }
    }

    // ---- rowsum reduce: quad shuffle + smem atomics ----
    rs0 += __shfl_xor_sync(0xffffffffu, rs0, 1);
    rs0 += __shfl_xor_sync(0xffffffffu, rs0, 2);
    rs1 += __shfl_xor_sync(0xffffffffu, rs1, 1);
    rs1 += __shfl_xor_sync(0xffffffffu, rs1, 2);
    if ((l & 3) == 0) {
        atomicAdd(&rsum_s[r0], rs0);
        atomicAdd(&rsum_s[r0 + 8], rs1);
    }
    __syncthreads();

    if (tid < QT) g_inv[(size_t)bh * SS + q0 + tid] = 1.0f / rsum_s[tid];

    if (ctx_out) {
        float i0 = 1.0f / rsum_s[r0];
        float i1 = 1.0f / rsum_s[r0 + 8];
#pragma unroll
        for (int t = 0; t < 2; t++) {
            int cl = 16 * ns + 8 * t + (l & 3) * 2;
            *(float2*)(ctx_out + ((size_t)bh * SS + q0 + r0) * DD + cl) =
                make_float2((pvM[t][0] + pvL[t][0]) * i0, (pvM[t][1] + pvL[t][1]) * i0);
            *(float2*)(ctx_out + ((size_t)bh * SS + q0 + r0 + 8) * DD + cl) =
                make_float2((pvM[t][2] + pvL[t][2]) * i1, (pvM[t][3] + pvL[t][3]) * i1);
        }
    }
}

// ---------------- normalize probs: prob[row,:] *= g_inv[row] ------------------
__global__ __launch_bounds__(256)
void norm_kernel(float* __restrict__ prob)
{
    const int row = blockIdx.x;
    const float inv = g_inv[row];
    float4* p = (float4*)(prob + (size_t)row * SS);
    int t = threadIdx.x;
#pragma unroll
    for (int it = 0; it < 2; it++) {
        float4 v = p[t + 256 * it];
        v.x *= inv; v.y *= inv; v.z *= inv; v.w *= inv;
        p[t + 256 * it] = v;
    }
}

extern "C" void kernel_launch(void* const* d_in, const int* in_sizes, int n_in,
                              void* d_out, int out_size)
{
    const float* Q = (const float*)d_in[0];
    const float* K = (const float*)d_in[1];
    const float* V = (const float*)d_in[2];
    const int*   M = (const int*)d_in[3];

    float* ctx = nullptr;
    float* prob = nullptr;
    long long os = out_size;
    if (os >= (long long)(CTX_ELEMS + PROB_ELEMS)) {
        ctx  = (float*)d_out;
        prob = (float*)d_out + CTX_ELEMS;
    } else if (os == (long long)PROB_ELEMS) {
        prob = (float*)d_out;
    } else {
        ctx  = (float*)d_out;
    }

    static bool attr_set = false;
    if (!attr_set) {
        cudaFuncSetAttribute(sdpa_stream_kernel,
                             cudaFuncAttributeMaxDynamicSharedMemorySize, SMEM_BYTES);
        attr_set = true;
    }

    prep_split_kernel<<<(NBH * SS * DD) / 256, 256>>>(K, V);
    sdpa_stream_kernel<<<NBH * (SS / QT), 256, SMEM_BYTES>>>(Q, M, ctx, prob);
    if (prob) norm_kernel<<<NBH * SS, 256>>>(prob);
}

// round 6
// speedup vs baseline: 5.1776x; 1.2612x over previous
#include <cuda_runtime.h>
#include <cuda_bf16.h>
#include <cstdint>

#define SS 2048
#define DD 64
#define NBH 32
#define QT 32
#define KCH 64
#define NCH (SS/KCH)                    // 32
#define C_EXP 0.18033688011112042f      // 0.125 * log2(e)

#define CTX_ELEMS (2LL*16*2048*64)
#define PROB_ELEMS (2LL*16*2048*2048)

// ---------------- device-global scratch (allowed) -----------------------------
__device__ __nv_bfloat16 g_khi[NBH*SS*DD];
__device__ __nv_bfloat16 g_klo[NBH*SS*DD];
__device__ __nv_bfloat16 g_vhi[NBH*SS*DD];
__device__ __nv_bfloat16 g_vlo[NBH*SS*DD];

__global__ void prep_split_kernel(const float* __restrict__ K,
                                  const float* __restrict__ V)
{
    int i = blockIdx.x * 256 + threadIdx.x;
    float k = K[i];
    __nv_bfloat16 kh = __float2bfloat16(k);
    g_khi[i] = kh;
    g_klo[i] = __float2bfloat16(k - __bfloat162float(kh));
    float v = V[i];
    __nv_bfloat16 vh = __float2bfloat16(v);
    g_vhi[i] = vh;
    g_vlo[i] = __float2bfloat16(v - __bfloat162float(vh));
}

// ---------------- smem layout (bytes) ----------------------------------------
// buf0: khi|klo|vhi|vlo, each 64 rows x 72 bf16 (144B stride) = 9216 each
#define ARR_B   9216
#define BUF_B   (4*ARR_B)               // 36864
#define OFF_BUF0 0
#define OFF_BUF1 36864
#define OFF_Q    73728                  // qhi 4608 | qlo 4608
#define OFF_MASK 82944                  // 2048
#define OFF_RSUM 84992                  // 32 floats
#define OFF_RINV 85120                  // 32 floats
#define SMEM_BYTES 85248

__device__ __forceinline__ uint32_t sptr(const void* p) {
    return (uint32_t)__cvta_generic_to_shared(p);
}
__device__ __forceinline__ void ldmA(uint32_t* a, uint32_t addr) {
    asm volatile("ldmatrix.sync.aligned.m8n8.x4.shared.b16 {%0,%1,%2,%3}, [%4];"
                 : "=r"(a[0]), "=r"(a[1]), "=r"(a[2]), "=r"(a[3]) : "r"(addr));
}
__device__ __forceinline__ void ldmB(uint32_t* b, uint32_t addr) {
    asm volatile("ldmatrix.sync.aligned.m8n8.x2.shared.b16 {%0,%1}, [%2];"
                 : "=r"(b[0]), "=r"(b[1]) : "r"(addr));
}
__device__ __forceinline__ void ldmBT(uint32_t* b, uint32_t addr) {
    asm volatile("ldmatrix.sync.aligned.m8n8.x2.trans.shared.b16 {%0,%1}, [%2];"
                 : "=r"(b[0]), "=r"(b[1]) : "r"(addr));
}
__device__ __forceinline__ void mma16816(float* c, const uint32_t* a, const uint32_t* b) {
    asm volatile("mma.sync.aligned.m16n8k16.row.col.f32.bf16.bf16.f32 "
                 "{%0,%1,%2,%3}, {%4,%5,%6,%7}, {%8,%9}, {%0,%1,%2,%3};"
                 : "+f"(c[0]), "+f"(c[1]), "+f"(c[2]), "+f"(c[3])
                 : "r"(a[0]), "r"(a[1]), "r"(a[2]), "r"(a[3]), "r"(b[0]), "r"(b[1]));
}
__device__ __forceinline__ void cpa16(uint32_t dst, const void* src) {
    asm volatile("cp.async.cg.shared.global [%0], [%1], 16;" :: "r"(dst), "l"(src));
}
__device__ __forceinline__ void cpa_commit() {
    asm volatile("cp.async.commit_group;");
}
template<int N> __device__ __forceinline__ void cpa_wait() {
    asm volatile("cp.async.wait_group %0;" :: "n"(N));
}
__device__ __forceinline__ float ex2f(float x) {
    float y; asm("ex2.approx.f32 %0, %1;" : "=f"(y) : "f"(x)); return y;
}
__device__ __forceinline__ uint32_t packbf2(float a, float b) {
    __nv_bfloat162 t = __floats2bfloat162_rn(a, b);
    return *(uint32_t*)&t;
}

__global__ __launch_bounds__(256, 2)
void sdpa_stream_kernel(const float* __restrict__ Qg_,
                        const int*   __restrict__ Mg_,
                        float* __restrict__ ctx_out,
                        float* __restrict__ prob_out)
{
    extern __shared__ char smem[];
    __nv_bfloat16* qhi_s = (__nv_bfloat16*)(smem + OFF_Q);
    __nv_bfloat16* qlo_s = qhi_s + 2304;
    unsigned char* maskc = (unsigned char*)(smem + OFF_MASK);
    float* rsum_s = (float*)(smem + OFF_RSUM);
    float* rinv_s = (float*)(smem + OFF_RINV);

    const int tid = threadIdx.x;
    const int w = tid >> 5, l = tid & 31;
    const int bh = blockIdx.x >> 6;
    const int qt = blockIdx.x & 63;
    const int q0 = qt * QT;
    const int b  = bh >> 4;
    const int mh = w & 1;               // m-half: rows 16*mh..
    const int ns = w >> 1;              // k-slice 16*ns.. (0..3)
    const int lr = l >> 2;
    const int lc = (l & 3) * 2;
    const int r0 = 16 * mh + lr;

    const float* Qg = Qg_ + ((size_t)bh * SS + q0) * DD;
    const int*   mg = Mg_ + (size_t)b * SS;

    // ---- init: Q split into smem, mask, rowsums ----
    for (int i = tid; i < QT * DD; i += 256) {
        int r = i >> 6, d = i & 63;
        float x = Qg[i];
        __nv_bfloat16 h = __float2bfloat16(x);
        qhi_s[r * 72 + d] = h;
        qlo_s[r * 72 + d] = __float2bfloat16(x - __bfloat162float(h));
    }
    for (int i = tid; i < SS; i += 256) maskc[i] = (mg[i] != 0) ? 1 : 0;
    if (tid < QT) rsum_s[tid] = 0.f;
    __syncthreads();

    // ---- Q fragments -> registers (reused across all chunks) ----
    uint32_t qh[16], ql[16];
    {
        uint32_t qb = sptr(qhi_s) + (16 * mh + (l & 15)) * 144 + (l >> 4) * 16;
#pragma unroll
        for (int kt = 0; kt < 4; kt++) {
            ldmA(qh + 4 * kt, qb + kt * 32);
            ldmA(ql + 4 * kt, qb + 4608 + kt * 32);
        }
    }

    const __nv_bfloat16* gkh = g_khi + (size_t)bh * SS * DD;
    const __nv_bfloat16* gkl = g_klo + (size_t)bh * SS * DD;
    const __nv_bfloat16* gvh = g_vhi + (size_t)bh * SS * DD;
    const __nv_bfloat16* gvl = g_vlo + (size_t)bh * SS * DD;
    const uint32_t smem_base = sptr(smem);

    // stage one chunk (4 arrays) into buffer `off` with cp.async
    auto issue = [&](uint32_t off, int kb) {
#pragma unroll
        for (int rI = 0; rI < 8; rI++) {
            const __nv_bfloat16* g = (rI < 2) ? gkh : (rI < 4) ? gkl
                                   : (rI < 6) ? gvh : gvl;
            int rem = (rI & 1) * 256 + tid;         // 0..511
            int key = rem >> 3, seg = rem & 7;
            cpa16(smem_base + off + (rI >> 1) * ARR_B + key * 144 + seg * 16,
                  g + (size_t)(kb + key) * DD + seg * 8);
        }
        cpa_commit();
    };

    issue(OFF_BUF0, 0);

    const uint32_t kOff = (l & 7) * 144 + ((l >> 3) & 1) * 16;
    const uint32_t vRow = (16 * ns + (l & 15)) * 144;
    float* probRow = prob_out ? prob_out + ((size_t)bh * SS + q0 + r0) * SS : nullptr;

    float pv[8][4] = {};
    float rs0 = 0.f, rs1 = 0.f;

    for (int ch = 0; ch < NCH; ch++) {
        const uint32_t bufo = (ch & 1) ? OFF_BUF1 : OFF_BUF0;
        if (ch + 1 < NCH) {
            issue((ch & 1) ? OFF_BUF0 : OFF_BUF1, (ch + 1) * KCH);
            cpa_wait<1>();
        } else {
            cpa_wait<0>();
        }
        __syncthreads();

        // ---- QK^T: warp -> rows 16mh..+15, keys 16ns..+15 (2 n8 tiles) ----
        const uint32_t kbase = smem_base + bufo;
        float acc[2][4] = {};
        uint32_t bhf[2], blf[2];
#pragma unroll
        for (int kt = 0; kt < 4; kt++) {
#pragma unroll
            for (int t = 0; t < 2; t++) {
                uint32_t nb = (16 * ns + 8 * t) * 144 + kOff + kt * 32;
                ldmB(bhf, kbase + nb);
                ldmB(blf, kbase + ARR_B + nb);
                mma16816(acc[t], qh + 4 * kt, bhf);
                mma16816(acc[t], qh + 4 * kt, blf);
                mma16816(acc[t], ql + 4 * kt, bhf);
            }
        }

        // ---- epilogue: exp, mask, prob write, pack P into A-frags ----
        const int kb = ch * KCH;
        uint32_t pah[4], pal[4];
#pragma unroll
        for (int t = 0; t < 2; t++) {
            int cl = 16 * ns + 8 * t + lc;
            int cg = kb + cl;
            uchar2 mm = *(uchar2*)(maskc + cg);
            float p0 = mm.x ? 0.f : ex2f(acc[t][0] * C_EXP);
            float p1 = mm.y ? 0.f : ex2f(acc[t][1] * C_EXP);
            float p2 = mm.x ? 0.f : ex2f(acc[t][2] * C_EXP);
            float p3 = mm.y ? 0.f : ex2f(acc[t][3] * C_EXP);
            rs0 += p0 + p1;
            rs1 += p2 + p3;
            if (probRow) {
                *(float2*)(probRow + cg)          = make_float2(p0, p1);
                *(float2*)(probRow + 8 * SS + cg) = make_float2(p2, p3);
            }
            uint32_t h01 = packbf2(p0, p1), h23 = packbf2(p2, p3);
            pah[2 * t]     = h01;
            pah[2 * t + 1] = h23;
            __nv_bfloat162 b01 = *(__nv_bfloat162*)&h01;
            __nv_bfloat162 b23 = *(__nv_bfloat162*)&h23;
            pal[2 * t]     = packbf2(p0 - __bfloat162float(b01.x),
                                     p1 - __bfloat162float(b01.y));
            pal[2 * t + 1] = packbf2(p2 - __bfloat162float(b23.x),
                                     p3 - __bfloat162float(b23.y));
        }

        // ---- PV: warp's k16 slice x all 64 dims (partial accumulation) ----
        const uint32_t vbase = kbase + 2 * ARR_B + vRow;
#pragma unroll
        for (int j = 0; j < 8; j++) {
            ldmBT(bhf, vbase + j * 16);
            ldmBT(blf, vbase + ARR_B + j * 16);
            mma16816(pv[j], pah, bhf);
            mma16816(pv[j], pah, blf);
            mma16816(pv[j], pal, bhf);
        }
        __syncthreads();
    }

    // ---- rowsum reduce ----
    rs0 += __shfl_xor_sync(0xffffffffu, rs0, 1);
    rs0 += __shfl_xor_sync(0xffffffffu, rs0, 2);
    rs1 += __shfl_xor_sync(0xffffffffu, rs1, 1);
    rs1 += __shfl_xor_sync(0xffffffffu, rs1, 2);
    if ((l & 3) == 0) {
        atomicAdd(&rsum_s[r0], rs0);
        atomicAdd(&rsum_s[r0 + 8], rs1);
    }
    __syncthreads();                    // (A) atomics done; staging free

    if (tid < QT) rinv_s[tid] = 1.0f / rsum_s[tid];

    // ---- cross-warp PV reduction: ns>0 write partials (reuse staging smem) --
    float* part = (float*)smem;         // 96 rows x 66 floats
    if (ns > 0) {
        int pr = (ns - 1) * 32 + 16 * mh + lr;
#pragma unroll
        for (int j = 0; j < 8; j++) {
            *(float2*)(part + pr * 66 + 8 * j + lc)       = make_float2(pv[j][0], pv[j][1]);
            *(float2*)(part + (pr + 8) * 66 + 8 * j + lc) = make_float2(pv[j][2], pv[j][3]);
        }
    }
    __syncthreads();                    // (B)

    if (ns == 0 && ctx_out) {
#pragma unroll
        for (int j = 0; j < 8; j++) {
#pragma unroll
            for (int s = 0; s < 3; s++) {
                int pr = s * 32 + 16 * mh + lr;
                float2 u  = *(float2*)(part + pr * 66 + 8 * j + lc);
                float2 u2 = *(float2*)(part + (pr + 8) * 66 + 8 * j + lc);
                pv[j][0] += u.x;  pv[j][1] += u.y;
                pv[j][2] += u2.x; pv[j][3] += u2.y;
            }
        }
        float i0 = rinv_s[r0], i1 = rinv_s[r0 + 8];
        float* c0 = ctx_out + ((size_t)bh * SS + q0 + r0) * DD;
#pragma unroll
        for (int j = 0; j < 8; j++) {
            *(float2*)(c0 + 8 * j + lc) =
                make_float2(pv[j][0] * i0, pv[j][1] * i0);
            *(float2*)(c0 + 8 * DD + 8 * j + lc) =
                make_float2(pv[j][2] * i1, pv[j][3] * i1);
        }
    }

    // ---- tail: normalize this block's prob rows (L2-resident RMW) ----
    if (prob_out) {
        float* pbase = prob_out + ((size_t)bh * SS + q0) * SS;
#pragma unroll 4
        for (int i = tid; i < QT * (SS / 4); i += 256) {
            int row = i >> 9;
            int c = (i & 511) * 4;
            float inv = rinv_s[row];
            float4 v = *(float4*)(pbase + (size_t)row * SS + c);
            v.x *= inv; v.y *= inv; v.z *= inv; v.w *= inv;
            *(float4*)(pbase + (size_t)row * SS + c) = v;
        }
    }
}

extern "C" void kernel_launch(void* const* d_in, const int* in_sizes, int n_in,
                              void* d_out, int out_size)
{
    const float* Q = (const float*)d_in[0];
    const float* K = (const float*)d_in[1];
    const float* V = (const float*)d_in[2];
    const int*   M = (const int*)d_in[3];

    float* ctx = nullptr;
    float* prob = nullptr;
    long long os = out_size;
    if (os >= (long long)(CTX_ELEMS + PROB_ELEMS)) {
        ctx  = (float*)d_out;
        prob = (float*)d_out + CTX_ELEMS;
    } else if (os == (long long)PROB_ELEMS) {
        prob = (float*)d_out;
    } else {
        ctx  = (float*)d_out;
    }

    static bool attr_set = false;
    if (!attr_set) {
        cudaFuncSetAttribute(sdpa_stream_kernel,
                             cudaFuncAttributeMaxDynamicSharedMemorySize, SMEM_BYTES);
        attr_set = true;
    }

    prep_split_kernel<<<(NBH * SS * DD) / 256, 256>>>(K, V);
    sdpa_stream_kernel<<<NBH * (SS / QT), 256, SMEM_BYTES>>>(Q, M, ctx, prob);
}

// round 7
// speedup vs baseline: 5.9179x; 1.1430x over previous
#include <cuda_runtime.h>
#include <cuda_fp16.h>
#include <cstdint>

#define SS 2048
#define DD 64
#define NBH 32
#define QT 32
#define KCH 64
#define NCH (SS/KCH)                    // 32
#define C_EXP 0.18033688011112042f      // 0.125 * log2(e)

#define CTX_ELEMS (2LL*16*2048*64)
#define PROB_ELEMS (2LL*16*2048*2048)

// ---------------- device-global scratch (allowed) -----------------------------
__device__ __half g_kh[NBH*SS*DD];
__device__ __half g_kl[NBH*SS*DD];
__device__ __half g_vh[NBH*SS*DD];

__global__ void prep_split_kernel(const float* __restrict__ K,
                                  const float* __restrict__ V)
{
    int i = blockIdx.x * 256 + threadIdx.x;
    float k = K[i];
    __half kh = __float2half_rn(k);
    g_kh[i] = kh;
    g_kl[i] = __float2half_rn(k - __half2float(kh));
    g_vh[i] = __float2half_rn(V[i]);
}

// ---------------- smem layout (bytes) ----------------------------------------
// buffer: kh | kl | vh, each 64 rows x 72 half (144B stride) = 9216
#define ARR_B   9216
#define BUF_B   (3*ARR_B)               // 27648
#define OFF_BUF0 0
#define OFF_BUF1 27648
#define OFF_Q    55296                  // qhi 4608 | qlo 4608
#define OFF_MASK 64512                  // 2048
#define OFF_RSUM 66560
#define OFF_RINV 66688
#define SMEM_BYTES 66816

__device__ __forceinline__ uint32_t sptr(const void* p) {
    return (uint32_t)__cvta_generic_to_shared(p);
}
__device__ __forceinline__ void ldmA(uint32_t* a, uint32_t addr) {
    asm volatile("ldmatrix.sync.aligned.m8n8.x4.shared.b16 {%0,%1,%2,%3}, [%4];"
                 : "=r"(a[0]), "=r"(a[1]), "=r"(a[2]), "=r"(a[3]) : "r"(addr));
}
__device__ __forceinline__ void ldmB(uint32_t* b, uint32_t addr) {
    asm volatile("ldmatrix.sync.aligned.m8n8.x2.shared.b16 {%0,%1}, [%2];"
                 : "=r"(b[0]), "=r"(b[1]) : "r"(addr));
}
__device__ __forceinline__ void ldmBT(uint32_t* b, uint32_t addr) {
    asm volatile("ldmatrix.sync.aligned.m8n8.x2.trans.shared.b16 {%0,%1}, [%2];"
                 : "=r"(b[0]), "=r"(b[1]) : "r"(addr));
}
__device__ __forceinline__ void mma16816(float* c, const uint32_t* a, const uint32_t* b) {
    asm volatile("mma.sync.aligned.m16n8k16.row.col.f32.f16.f16.f32 "
                 "{%0,%1,%2,%3}, {%4,%5,%6,%7}, {%8,%9}, {%0,%1,%2,%3};"
                 : "+f"(c[0]), "+f"(c[1]), "+f"(c[2]), "+f"(c[3])
                 : "r"(a[0]), "r"(a[1]), "r"(a[2]), "r"(a[3]), "r"(b[0]), "r"(b[1]));
}
__device__ __forceinline__ void cpa16(uint32_t dst, const void* src) {
    asm volatile("cp.async.cg.shared.global [%0], [%1], 16;" :: "r"(dst), "l"(src));
}
__device__ __forceinline__ void cpa_commit() {
    asm volatile("cp.async.commit_group;");
}
template<int N> __device__ __forceinline__ void cpa_wait() {
    asm volatile("cp.async.wait_group %0;" :: "n"(N));
}
__device__ __forceinline__ float ex2f(float x) {
    float y; asm("ex2.approx.f32 %0, %1;" : "=f"(y) : "f"(x)); return y;
}
__device__ __forceinline__ uint32_t packh2(float a, float b) {
    __half2 t = __floats2half2_rn(a, b);
    return *(uint32_t*)&t;
}

__global__ __launch_bounds__(256, 2)
void sdpa_stream_kernel(const float* __restrict__ Qg_,
                        const int*   __restrict__ Mg_,
                        float* __restrict__ ctx_out,
                        float* __restrict__ prob_out)
{
    extern __shared__ char smem[];
    __half* qhi_s = (__half*)(smem + OFF_Q);
    __half* qlo_s = qhi_s + 2304;
    unsigned char* maskc = (unsigned char*)(smem + OFF_MASK);
    float* rsum_s = (float*)(smem + OFF_RSUM);
    float* rinv_s = (float*)(smem + OFF_RINV);

    const int tid = threadIdx.x;
    const int w = tid >> 5, l = tid & 31;
    const int bh = blockIdx.x >> 6;
    const int qt = blockIdx.x & 63;
    const int q0 = qt * QT;
    const int b  = bh >> 4;
    const int mh = w & 1;               // m-half: rows 16*mh..
    const int ns = w >> 1;              // k-slice 16*ns.. (0..3)
    const int lr = l >> 2;
    const int lc = (l & 3) * 2;
    const int r0 = 16 * mh + lr;

    const float* Qg = Qg_ + ((size_t)bh * SS + q0) * DD;
    const int*   mg = Mg_ + (size_t)b * SS;

    // ---- init: Q split (fp16 hi/lo) into smem, mask, rowsums ----
    for (int i = tid; i < QT * DD; i += 256) {
        int r = i >> 6, d = i & 63;
        float x = Qg[i];
        __half h = __float2half_rn(x);
        qhi_s[r * 72 + d] = h;
        qlo_s[r * 72 + d] = __float2half_rn(x - __half2float(h));
    }
    for (int i = tid; i < SS; i += 256) maskc[i] = (mg[i] != 0) ? 1 : 0;
    if (tid < QT) rsum_s[tid] = 0.f;
    __syncthreads();

    // ---- Q fragments -> registers (reused across all chunks) ----
    uint32_t qh[16], ql[16];
    {
        uint32_t qb = sptr(qhi_s) + (16 * mh + (l & 15)) * 144 + (l >> 4) * 16;
#pragma unroll
        for (int kt = 0; kt < 4; kt++) {
            ldmA(qh + 4 * kt, qb + kt * 32);
            ldmA(ql + 4 * kt, qb + 4608 + kt * 32);
        }
    }

    const __half* gkh = g_kh + (size_t)bh * SS * DD;
    const __half* gkl = g_kl + (size_t)bh * SS * DD;
    const __half* gvh = g_vh + (size_t)bh * SS * DD;
    const uint32_t smem_base = sptr(smem);

    auto issue = [&](uint32_t off, int kb) {
#pragma unroll
        for (int rI = 0; rI < 6; rI++) {
            const __half* g = (rI < 2) ? gkh : (rI < 4) ? gkl : gvh;
            int rem = (rI & 1) * 256 + tid;          // 0..511
            int key = rem >> 3, seg = rem & 7;
            cpa16(smem_base + off + (rI >> 1) * ARR_B + key * 144 + seg * 16,
                  g + (size_t)(kb + key) * DD + seg * 8);
        }
        cpa_commit();
    };

    issue(OFF_BUF0, 0);

    const uint32_t kOff = (l & 7) * 144 + ((l >> 3) & 1) * 16;
    const uint32_t vRow = (16 * ns + (l & 15)) * 144;
    float* probRow = prob_out ? prob_out + ((size_t)bh * SS + q0 + r0) * SS : nullptr;

    float pv[8][4] = {};
    float rs0 = 0.f, rs1 = 0.f;

    for (int ch = 0; ch < NCH; ch++) {
        const uint32_t bufo = (ch & 1) ? OFF_BUF1 : OFF_BUF0;
        cpa_wait<0>();
        __syncthreads();                 // buffer visible; prior iter reads done
        if (ch + 1 < NCH)
            issue((ch & 1) ? OFF_BUF0 : OFF_BUF1, (ch + 1) * KCH);

        // ---- QK^T: rows 16mh..+15, keys 16ns..+15; dual accumulators ----
        const uint32_t kbase = smem_base + bufo;
        float accM[2][4] = {}, accL[2][4] = {};
        uint32_t bhf[2], blf[2];
#pragma unroll
        for (int kt = 0; kt < 4; kt++) {
#pragma unroll
            for (int t = 0; t < 2; t++) {
                uint32_t nb = (16 * ns + 8 * t) * 144 + kOff + kt * 32;
                ldmB(bhf, kbase + nb);
                ldmB(blf, kbase + ARR_B + nb);
                mma16816(accM[t], qh + 4 * kt, bhf);   // hh
                mma16816(accL[t], qh + 4 * kt, blf);   // h·lo
                mma16816(accL[t], ql + 4 * kt, bhf);   // lo·h
            }
        }

        // ---- epilogue: exp, mask, prob write, pack P (fp16 hi/lo) ----
        const int kb = ch * KCH;
        uint32_t pah[4], pal[4];
#pragma unroll
        for (int t = 0; t < 2; t++) {
            int cl = 16 * ns + 8 * t + lc;
            int cg = kb + cl;
            uchar2 mm = *(uchar2*)(maskc + cg);
            float p0 = mm.x ? 0.f : ex2f((accM[t][0] + accL[t][0]) * C_EXP);
            float p1 = mm.y ? 0.f : ex2f((accM[t][1] + accL[t][1]) * C_EXP);
            float p2 = mm.x ? 0.f : ex2f((accM[t][2] + accL[t][2]) * C_EXP);
            float p3 = mm.y ? 0.f : ex2f((accM[t][3] + accL[t][3]) * C_EXP);
            rs0 += p0 + p1;
            rs1 += p2 + p3;
            if (probRow) {
                *(float2*)(probRow + cg)          = make_float2(p0, p1);
                *(float2*)(probRow + 8 * SS + cg) = make_float2(p2, p3);
            }
            uint32_t h01 = packh2(p0, p1), h23 = packh2(p2, p3);
            pah[2 * t]     = h01;
            pah[2 * t + 1] = h23;
            __half2 b01 = *(__half2*)&h01;
            __half2 b23 = *(__half2*)&h23;
            pal[2 * t]     = packh2(p0 - __half2float(b01.x),
                                    p1 - __half2float(b01.y));
            pal[2 * t + 1] = packh2(p2 - __half2float(b23.x),
                                    p3 - __half2float(b23.y));
        }

        // ---- PV: warp's k16 slice x all 64 dims; V single fp16 ----
        const uint32_t vbase = kbase + 2 * ARR_B + vRow;
#pragma unroll
        for (int j = 0; j < 8; j++) {
            ldmBT(bhf, vbase + j * 16);
            mma16816(pv[j], pah, bhf);
            mma16816(pv[j], pal, bhf);
        }
    }

    // ---- rowsum reduce ----
    rs0 += __shfl_xor_sync(0xffffffffu, rs0, 1);
    rs0 += __shfl_xor_sync(0xffffffffu, rs0, 2);
    rs1 += __shfl_xor_sync(0xffffffffu, rs1, 1);
    rs1 += __shfl_xor_sync(0xffffffffu, rs1, 2);
    if ((l & 3) == 0) {
        atomicAdd(&rsum_s[r0], rs0);
        atomicAdd(&rsum_s[r0 + 8], rs1);
    }
    __syncthreads();                    // (A) all PV reads + atomics done

    if (tid < QT) rinv_s[tid] = 1.0f / rsum_s[tid];

    // ---- cross-warp PV reduction (reuse staging smem) ----
    float* part = (float*)smem;         // 96 rows x 66 floats = 25344B < staging
    if (ns > 0) {
        int pr = (ns - 1) * 32 + 16 * mh + lr;
#pragma unroll
        for (int j = 0; j < 8; j++) {
            *(float2*)(part + pr * 66 + 8 * j + lc)       = make_float2(pv[j][0], pv[j][1]);
            *(float2*)(part + (pr + 8) * 66 + 8 * j + lc) = make_float2(pv[j][2], pv[j][3]);
        }
    }
    __syncthreads();                    // (B)

    if (ns == 0 && ctx_out) {
#pragma unroll
        for (int j = 0; j < 8; j++) {
#pragma unroll
            for (int s = 0; s < 3; s++) {
                int pr = s * 32 + 16 * mh + lr;
                float2 u  = *(float2*)(part + pr * 66 + 8 * j + lc);
                float2 u2 = *(float2*)(part + (pr + 8) * 66 + 8 * j + lc);
                pv[j][0] += u.x;  pv[j][1] += u.y;
                pv[j][2] += u2.x; pv[j][3] += u2.y;
            }
        }
        float i0 = rinv_s[r0], i1 = rinv_s[r0 + 8];
        float* c0 = ctx_out + ((size_t)bh * SS + q0 + r0) * DD;
#pragma unroll
        for (int j = 0; j < 8; j++) {
            *(float2*)(c0 + 8 * j + lc) =
                make_float2(pv[j][0] * i0, pv[j][1] * i0);
            *(float2*)(c0 + 8 * DD + 8 * j + lc) =
                make_float2(pv[j][2] * i1, pv[j][3] * i1);
        }
    }

    // ---- tail: normalize this block's prob rows (mostly L2-resident RMW) ----
    if (prob_out) {
        float* pbase = prob_out + ((size_t)bh * SS + q0) * SS;
#pragma unroll 4
        for (int i = tid; i < QT * (SS / 4); i += 256) {
            int row = i >> 9;
            int c = (i & 511) * 4;
            float inv = rinv_s[row];
            float4 v = *(float4*)(pbase + (size_t)row * SS + c);
            v.x *= inv; v.y *= inv; v.z *= inv; v.w *= inv;
            *(float4*)(pbase + (size_t)row * SS + c) = v;
        }
    }
}

extern "C" void kernel_launch(void* const* d_in, const int* in_sizes, int n_in,
                              void* d_out, int out_size)
{
    const float* Q = (const float*)d_in[0];
    const float* K = (const float*)d_in[1];
    const float* V = (const float*)d_in[2];
    const int*   M = (const int*)d_in[3];

    float* ctx = nullptr;
    float* prob = nullptr;
    long long os = out_size;
    if (os >= (long long)(CTX_ELEMS + PROB_ELEMS)) {
        ctx  = (float*)d_out;
        prob = (float*)d_out + CTX_ELEMS;
    } else if (os == (long long)PROB_ELEMS) {
        prob = (float*)d_out;
    } else {
        ctx  = (float*)d_out;
    }

    static bool attr_set = false;
    if (!attr_set) {
        cudaFuncSetAttribute(sdpa_stream_kernel,
                             cudaFuncAttributeMaxDynamicSharedMemorySize, SMEM_BYTES);
        attr_set = true;
    }

    prep_split_kernel<<<(NBH * SS * DD) / 256, 256>>>(K, V);
    sdpa_stream_kernel<<<NBH * (SS / QT), 256, SMEM_BYTES>>>(Q, M, ctx, prob);
}